// round 12
// baseline (speedup 1.0000x reference)
#include <cuda_runtime.h>
#include <cuda_fp16.h>
#include <cstdint>

#define V     50000
#define E     800000
#define BATCH 4
#define CIN   64
#define COUT  128
#define KORD  4
#define M_TOT (V * BATCH)          // 200000

// Feature panels: [r = v*4+b][i 0..63] as half  (layout == [v][c=b*64+i])
__device__ __align__(16) __half g_feat[KORD][(size_t)V * BATCH * CIN];
// W transposed to [p][o][i] as half
__device__ __align__(16) __half g_wT[KORD * COUT * CIN];
__device__ int g_rowptr[V + 1];
// fp32 partial-sum scratch for the split GEMM: [r][o]
__device__ __align__(16) float g_scratch[(size_t)M_TOT * COUT];

// ---------------------------------------------------------------------------
// 1) Transpose x (B, Cin, V) -> feat0[v*256 + c] (half)
// ---------------------------------------------------------------------------
__global__ void transpose_kernel(const float* __restrict__ x) {
    __shared__ float tile[32][33];
    int v0 = blockIdx.x * 32;
    int c0 = blockIdx.y * 32;
    int tx = threadIdx.x, ty = threadIdx.y;
    int v = v0 + tx;
    if (v < V) tile[ty][tx] = x[(size_t)(c0 + ty) * V + v];
    __syncthreads();
    int vv = v0 + ty;
    if (vv < V)
        g_feat[0][(size_t)vv * 256 + c0 + tx] = __float2half_rn(tile[tx][ty]);
}

// ---------------------------------------------------------------------------
// 2) row_ptr from sorted COO rows
// ---------------------------------------------------------------------------
__global__ void rowptr_kernel(const int* __restrict__ rows) {
    int r = blockIdx.x * blockDim.x + threadIdx.x;
    if (r > V) return;
    int lo = 0, hi = E;
    while (lo < hi) {
        int mid = (lo + hi) >> 1;
        if (rows[mid] < r) lo = mid + 1; else hi = mid;
    }
    g_rowptr[r] = lo;
}

// ---------------------------------------------------------------------------
// 2b) W (K, Cin, Cout) fp32 -> g_wT (K, Cout, Cin) fp16
// ---------------------------------------------------------------------------
__global__ void wconvert_kernel(const float* __restrict__ w) {
    int n = blockIdx.x * blockDim.x + threadIdx.x;   // < K*COUT*CIN = 32768
    int p = n >> 13;
    int rem = n & 8191;
    int o = rem >> 6;
    int i = rem & 63;
    g_wT[n] = __float2half_rn(w[p * (CIN * COUT) + i * COUT + o]);
}

// ---------------------------------------------------------------------------
// 3) SpMM on fp16 panels (at L2 roofline — unchanged)
// ---------------------------------------------------------------------------
__device__ __forceinline__ void acc_edge(float acc[8], uint4 t, float w) {
    const half2* h = (const half2*)&t;
    #pragma unroll
    for (int j = 0; j < 4; ++j) {
        float2 f = __half22float2(h[j]);
        acc[2*j]   += w * f.x;
        acc[2*j+1] += w * f.y;
    }
}

__global__ void spmm_kernel(const int* __restrict__ cols,
                            const float* __restrict__ vals,
                            int in_idx, int out_idx, int prev_idx, int cheb) {
    int r    = blockIdx.x * 8 + (threadIdx.x >> 5);
    int lane = threadIdx.x & 31;
    const uint4* xin  = (const uint4*)&g_feat[in_idx][0];
    uint4*       xout = (uint4*)&g_feat[out_idx][0];

    int e  = g_rowptr[r];
    int e1 = g_rowptr[r + 1];

    float acc[8];
    #pragma unroll
    for (int j = 0; j < 8; ++j) acc[j] = 0.f;

    while (e + 4 <= e1) {
        int   c0 = __ldg(cols + e),     c1 = __ldg(cols + e + 1);
        int   c2 = __ldg(cols + e + 2), c3 = __ldg(cols + e + 3);
        float w0 = __ldg(vals + e),     w1 = __ldg(vals + e + 1);
        float w2 = __ldg(vals + e + 2), w3 = __ldg(vals + e + 3);
        uint4 t0 = xin[(size_t)c0 * 32 + lane];
        uint4 t1 = xin[(size_t)c1 * 32 + lane];
        uint4 t2 = xin[(size_t)c2 * 32 + lane];
        uint4 t3 = xin[(size_t)c3 * 32 + lane];
        acc_edge(acc, t0, w0);
        acc_edge(acc, t1, w1);
        acc_edge(acc, t2, w2);
        acc_edge(acc, t3, w3);
        e += 4;
    }
    while (e < e1) {
        int   c = __ldg(cols + e);
        float w = __ldg(vals + e);
        uint4 t = xin[(size_t)c * 32 + lane];
        acc_edge(acc, t, w);
        ++e;
    }

    size_t o = (size_t)r * 32 + lane;
    if (cheb) {
        uint4 pv = ((const uint4*)&g_feat[prev_idx][0])[o];
        const half2* h = (const half2*)&pv;
        #pragma unroll
        for (int j = 0; j < 4; ++j) {
            float2 f = __half22float2(h[j]);
            acc[2*j]   = 2.f * acc[2*j]   - f.x;
            acc[2*j+1] = 2.f * acc[2*j+1] - f.y;
        }
    }
    uint4 res;
    half2* rh = (half2*)&res;
    #pragma unroll
    for (int j = 0; j < 4; ++j)
        rh[j] = __floats2half2_rn(acc[2*j], acc[2*j+1]);
    xout[o] = res;
}

// ---------------------------------------------------------------------------
// 4) fp16 tensor-core GEMM over 2 panels, 128x128 block tile, ldmatrix +
//    cp.async. 256 threads = 8 warps (4 m x 2 n); warp tile 32x64.
//    MODE 0: panels {pbase, pbase+1} -> g_scratch[r][o]          (no bias)
//    MODE 1: panels {pbase, pbase+1} + g_scratch + bias -> out   (transposed)
// ---------------------------------------------------------------------------
#define ASH 72                              // halfs per A smem row (64 + 8 pad)
#define WSH 72                              // halfs per W smem row
#define CSF 132                             // floats per C staging row (EVEN)
#define ABUF_BYTES (128 * ASH * 2)          // 18432
#define WBUF_BYTES (128 * WSH * 2)          // 18432
#define GEMM_SMEM  (2 * ABUF_BYTES + 2 * WBUF_BYTES)   // 73728
// C staging (64 rows x CSF floats = 33792 B) aliases the A/W buffers.

__device__ __forceinline__ void mma_f16(float c[4],
                                        uint32_t a0, uint32_t a1, uint32_t a2, uint32_t a3,
                                        uint32_t b0, uint32_t b1) {
    asm volatile(
        "mma.sync.aligned.m16n8k16.row.col.f32.f16.f16.f32 "
        "{%0,%1,%2,%3}, {%4,%5,%6,%7}, {%8,%9}, {%0,%1,%2,%3};"
        : "+f"(c[0]), "+f"(c[1]), "+f"(c[2]), "+f"(c[3])
        : "r"(a0), "r"(a1), "r"(a2), "r"(a3), "r"(b0), "r"(b1));
}

__device__ __forceinline__ void ldsm4(uint32_t f[4], uint32_t addr) {
    asm volatile("ldmatrix.sync.aligned.m8n8.x4.shared.b16 {%0,%1,%2,%3}, [%4];"
                 : "=r"(f[0]), "=r"(f[1]), "=r"(f[2]), "=r"(f[3]) : "r"(addr));
}

__device__ __forceinline__ void cp_async16(uint32_t dst, const void* src) {
    asm volatile("cp.async.cg.shared.global [%0], [%1], 16;" :: "r"(dst), "l"(src));
}
__device__ __forceinline__ void cp_commit() {
    asm volatile("cp.async.commit_group;");
}
template <int N>
__device__ __forceinline__ void cp_wait() {
    asm volatile("cp.async.wait_group %0;" :: "n"(N));
}

template <int MODE>
__global__ __launch_bounds__(256, 2)
void gemm_kernel(const float* __restrict__ bias, float* __restrict__ out,
                 int pbase) {
    extern __shared__ char smem_raw[];
    uint32_t smem_u32 = (uint32_t)__cvta_generic_to_shared(smem_raw);
    float* Cs = (float*)smem_raw;   // aliased staging, [64][CSF]

    int tid  = threadIdx.x;
    int wid  = tid >> 5, lane = tid & 31;
    int wm   = wid & 3;        // m-warp: rows wm*32 .. wm*32+31
    int wn   = wid >> 2;       // n-warp: cols wn*64 .. wn*64+63
    int m0   = blockIdx.x * 128;
    int g    = lane >> 2;      // 0..7
    int tg   = lane & 3;       // 0..3
    int lq   = lane & 15;      // ldmatrix row-select
    int lh   = (lane >> 4) << 3;

    uint32_t aoff[2] = { smem_u32,                smem_u32 + ABUF_BYTES };
    uint32_t woff[2] = { smem_u32 + 2*ABUF_BYTES, smem_u32 + 2*ABUF_BYTES + WBUF_BYTES };

    float acc[2][8][4];
    #pragma unroll
    for (int mt = 0; mt < 2; ++mt)
        #pragma unroll
        for (int nt = 0; nt < 8; ++nt)
            #pragma unroll
            for (int j = 0; j < 4; ++j) acc[mt][nt][j] = 0.f;

    auto prefetch = [&](int p, int buf) {
        const __half* Ap = &g_feat[p][0];
        #pragma unroll
        for (int i = 0; i < 4; ++i) {
            int idx  = i * 256 + tid;          // 0..1023
            int row  = idx >> 3;               // 0..127
            int col8 = (idx & 7) << 3;
            int rg   = m0 + row; if (rg > M_TOT - 1) rg = M_TOT - 1;
            cp_async16(aoff[buf] + (uint32_t)(row * ASH + col8) * 2,
                       Ap + (size_t)rg * 64 + col8);
        }
        const __half* wp = g_wT + p * (COUT * CIN);
        #pragma unroll
        for (int i = 0; i < 4; ++i) {
            int idx  = i * 256 + tid;
            int o    = idx >> 3;
            int col8 = (idx & 7) << 3;
            cp_async16(woff[buf] + (uint32_t)(o * WSH + col8) * 2,
                       wp + o * 64 + col8);
        }
        cp_commit();
    };

    prefetch(pbase, 0);
    prefetch(pbase + 1, 1);

    #pragma unroll
    for (int pi = 0; pi < 2; ++pi) {
        if (pi == 0) cp_wait<1>(); else cp_wait<0>();
        __syncthreads();
        uint32_t abase = aoff[pi];
        uint32_t wbase = woff[pi];
        #pragma unroll
        for (int ks = 0; ks < 4; ++ks) {
            int kb = ks * 16;
            uint32_t afr[2][4];
            #pragma unroll
            for (int mt = 0; mt < 2; ++mt)
                ldsm4(afr[mt], abase + (uint32_t)((wm*32 + mt*16 + lq) * ASH + kb + lh) * 2);
            uint32_t bfr[4][4];
            #pragma unroll
            for (int bp = 0; bp < 4; ++bp)
                ldsm4(bfr[bp], wbase + (uint32_t)((wn*64 + bp*16 + lq) * WSH + kb + lh) * 2);
            #pragma unroll
            for (int mt = 0; mt < 2; ++mt)
                #pragma unroll
                for (int bp = 0; bp < 4; ++bp) {
                    mma_f16(acc[mt][2*bp],   afr[mt][0], afr[mt][1], afr[mt][2], afr[mt][3],
                            bfr[bp][0], bfr[bp][2]);
                    mma_f16(acc[mt][2*bp+1], afr[mt][0], afr[mt][1], afr[mt][2], afr[mt][3],
                            bfr[bp][1], bfr[bp][3]);
                }
        }
        __syncthreads();
    }

    if (MODE == 0) {
        // Write partial sums to scratch [r][o], coalesced float2.
        #pragma unroll
        for (int mt = 0; mt < 2; ++mt) {
            int r0 = m0 + wm * 32 + mt * 16 + g;
            #pragma unroll
            for (int nt = 0; nt < 8; ++nt) {
                int c0 = wn * 64 + nt * 8 + 2 * tg;
                if (r0 < M_TOT)
                    *(float2*)&g_scratch[(size_t)r0 * COUT + c0] =
                        make_float2(acc[mt][nt][0], acc[mt][nt][1]);
                if (r0 + 8 < M_TOT)
                    *(float2*)&g_scratch[(size_t)(r0 + 8) * COUT + c0] =
                        make_float2(acc[mt][nt][2], acc[mt][nt][3]);
            }
        }
        return;
    }

    // MODE 1: add scratch partials
    #pragma unroll
    for (int mt = 0; mt < 2; ++mt) {
        int r0 = m0 + wm * 32 + mt * 16 + g;
        #pragma unroll
        for (int nt = 0; nt < 8; ++nt) {
            int c0 = wn * 64 + nt * 8 + 2 * tg;
            if (r0 < M_TOT) {
                float2 s = *(const float2*)&g_scratch[(size_t)r0 * COUT + c0];
                acc[mt][nt][0] += s.x; acc[mt][nt][1] += s.y;
            }
            if (r0 + 8 < M_TOT) {
                float2 s = *(const float2*)&g_scratch[(size_t)(r0 + 8) * COUT + c0];
                acc[mt][nt][2] += s.x; acc[mt][nt][3] += s.y;
            }
        }
    }

    // Epilogue: two 64-row chunks, staged via smem (aliases A/W buffers).
    #pragma unroll
    for (int ch = 0; ch < 2; ++ch) {
        __syncthreads();
        if ((wm >> 1) == ch) {
            int rbase = (wm & 1) * 32;
            #pragma unroll
            for (int mt = 0; mt < 2; ++mt) {
                int rl = rbase + mt * 16 + g;
                #pragma unroll
                for (int nt = 0; nt < 8; ++nt) {
                    int c0 = wn * 64 + nt * 8 + 2 * tg;
                    *(float2*)(Cs + rl * CSF + c0)       = make_float2(acc[mt][nt][0], acc[mt][nt][1]);
                    *(float2*)(Cs + (rl + 8) * CSF + c0) = make_float2(acc[mt][nt][2], acc[mt][nt][3]);
                }
            }
        }
        __syncthreads();

        int vbase = blockIdx.x * 32 + ch * 16;
        #pragma unroll
        for (int i = 0; i < 8; ++i) {
            int idx = i * 256 + tid;       // 0..2047
            int pr  = idx >> 2;            // (b,o) pair
            int q   = idx & 3;             // v quad
            int b   = pr & 3;
            int o   = pr >> 2;
            int v   = vbase + 4 * q;
            if (v < V) {
                float bv = __ldg(bias + o);
                float4 t;
                t.x = Cs[(16 * q + 0 * 4 + b) * CSF + o] + bv;
                t.y = Cs[(16 * q + 1 * 4 + b) * CSF + o] + bv;
                t.z = Cs[(16 * q + 2 * 4 + b) * CSF + o] + bv;
                t.w = Cs[(16 * q + 3 * 4 + b) * CSF + o] + bv;
                *(float4*)(out + ((size_t)b * COUT + o) * V + v) = t;
            }
        }
    }
}

// ---------------------------------------------------------------------------
// Launch: fork GEMM_A (panels 0,1 -> scratch) onto a second captured stream
// so it overlaps spmm2 + spmm3. rowptr/wconvert overlap the transpose.
// ---------------------------------------------------------------------------
extern "C" void kernel_launch(void* const* d_in, const int* in_sizes, int n_in,
                              void* d_out, int out_size) {
    const float* x    = (const float*)d_in[0];
    const int*   rows = (const int*)  d_in[1];
    const int*   cols = (const int*)  d_in[2];
    const float* vals = (const float*)d_in[3];
    const float* w    = (const float*)d_in[4];
    const float* bias = (const float*)d_in[5];
    float*       out  = (float*)d_out;

    (void)in_sizes; (void)n_in; (void)out_size;

    // One-time resource creation (host-side only; no device memory).
    static cudaStream_t s2 = nullptr;
    static cudaEvent_t ev0 = nullptr, evRW = nullptr, evP1 = nullptr, evA = nullptr;
    if (!s2) {
        cudaStreamCreateWithFlags(&s2, cudaStreamNonBlocking);
        cudaEventCreateWithFlags(&ev0,  cudaEventDisableTiming);
        cudaEventCreateWithFlags(&evRW, cudaEventDisableTiming);
        cudaEventCreateWithFlags(&evP1, cudaEventDisableTiming);
        cudaEventCreateWithFlags(&evA,  cudaEventDisableTiming);
    }

    // Resolve the stream the harness is (possibly) capturing.
    cudaStream_t cap = cudaStreamLegacy;
    {
        cudaStreamCaptureStatus st = cudaStreamCaptureStatusNone;
        cudaStreamIsCapturing(cudaStreamLegacy, &st);
        if (st != cudaStreamCaptureStatusActive) {
            cudaStreamCaptureStatus st2 = cudaStreamCaptureStatusNone;
            cudaStreamIsCapturing(cudaStreamPerThread, &st2);
            if (st2 == cudaStreamCaptureStatusActive) cap = cudaStreamPerThread;
        }
    }

    cudaFuncSetAttribute(gemm_kernel<0>,
                         cudaFuncAttributeMaxDynamicSharedMemorySize, GEMM_SMEM);
    cudaFuncSetAttribute(gemm_kernel<1>,
                         cudaFuncAttributeMaxDynamicSharedMemorySize, GEMM_SMEM);

    int gemm_blocks = (M_TOT + 127) / 128;

    // Fork point: s2 does rowptr + wconvert while cap transposes.
    cudaEventRecord(ev0, cap);
    cudaStreamWaitEvent(s2, ev0, 0);
    rowptr_kernel<<<(V + 1 + 255) / 256, 256, 0, s2>>>(rows);
    wconvert_kernel<<<(KORD * COUT * CIN) / 256, 256, 0, s2>>>(w);
    cudaEventRecord(evRW, s2);

    transpose_kernel<<<dim3((V + 31) / 32, 256 / 32), dim3(32, 32), 0, cap>>>(x);
    cudaStreamWaitEvent(cap, evRW, 0);

    spmm_kernel<<<V / 8, 256, 0, cap>>>(cols, vals, 0, 1, 0, 0);  // x1 = L x0
    cudaEventRecord(evP1, cap);

    // s2: GEMM_A over panels {0,1} -> scratch, overlapping spmm2 + spmm3.
    cudaStreamWaitEvent(s2, evP1, 0);
    gemm_kernel<0><<<gemm_blocks, 256, GEMM_SMEM, s2>>>(bias, out, 0);
    cudaEventRecord(evA, s2);

    spmm_kernel<<<V / 8, 256, 0, cap>>>(cols, vals, 1, 2, 0, 1);  // x2 = 2 L x1 - x0
    spmm_kernel<<<V / 8, 256, 0, cap>>>(cols, vals, 2, 3, 1, 1);  // x3 = 2 L x2 - x1

    // Join and finish: GEMM_B over panels {2,3} + scratch + bias -> out.
    cudaStreamWaitEvent(cap, evA, 0);
    gemm_kernel<1><<<gemm_blocks, 256, GEMM_SMEM, cap>>>(bias, out, 2);
}

// round 13
// speedup vs baseline: 1.6723x; 1.6723x over previous
#include <cuda_runtime.h>
#include <cuda_fp16.h>
#include <cstdint>

#define V     50000
#define E     800000
#define BATCH 4
#define CIN   64
#define COUT  128
#define KORD  4
#define M_TOT (V * BATCH)          // 200000

// Feature panels: [r = v*4+b][i 0..63] as half  (layout == [v][c=b*64+i])
__device__ __align__(16) __half g_feat[KORD][(size_t)V * BATCH * CIN];
// W transposed to [p][o][i] as half
__device__ __align__(16) __half g_wT[KORD * COUT * CIN];
__device__ int g_rowptr[V + 1];

// ---------------------------------------------------------------------------
// 1) Transpose x (B, Cin, V) -> feat0[v*256 + c] (half)
// ---------------------------------------------------------------------------
__global__ void transpose_kernel(const float* __restrict__ x) {
    __shared__ float tile[32][33];
    int v0 = blockIdx.x * 32;
    int c0 = blockIdx.y * 32;
    int tx = threadIdx.x, ty = threadIdx.y;
    int v = v0 + tx;
    if (v < V) tile[ty][tx] = x[(size_t)(c0 + ty) * V + v];
    __syncthreads();
    int vv = v0 + ty;
    if (vv < V)
        g_feat[0][(size_t)vv * 256 + c0 + tx] = __float2half_rn(tile[tx][ty]);
}

// ---------------------------------------------------------------------------
// 2) Fused prep: blocks [0,196) build row_ptr; blocks [196,324) convert W.
// ---------------------------------------------------------------------------
#define RP_BLOCKS 196              // ceil(50001/256)
#define WC_BLOCKS 128              // 32768/256
__global__ void prep_kernel(const int* __restrict__ rows,
                            const float* __restrict__ w) {
    if (blockIdx.x < RP_BLOCKS) {
        int r = blockIdx.x * 256 + threadIdx.x;
        if (r > V) return;
        int lo = 0, hi = E;
        while (lo < hi) {
            int mid = (lo + hi) >> 1;
            if (rows[mid] < r) lo = mid + 1; else hi = mid;
        }
        g_rowptr[r] = lo;
    } else {
        int n = (blockIdx.x - RP_BLOCKS) * 256 + threadIdx.x;  // < 32768
        int p = n >> 13;
        int rem = n & 8191;
        int o = rem >> 6;
        int i = rem & 63;
        g_wT[n] = __float2half_rn(w[p * (CIN * COUT) + i * COUT + o]);
    }
}

// ---------------------------------------------------------------------------
// 3) SpMM on fp16 panels (at L2 roofline — unchanged)
// ---------------------------------------------------------------------------
__device__ __forceinline__ void acc_edge(float acc[8], uint4 t, float w) {
    const half2* h = (const half2*)&t;
    #pragma unroll
    for (int j = 0; j < 4; ++j) {
        float2 f = __half22float2(h[j]);
        acc[2*j]   += w * f.x;
        acc[2*j+1] += w * f.y;
    }
}

__global__ void spmm_kernel(const int* __restrict__ cols,
                            const float* __restrict__ vals,
                            int in_idx, int out_idx, int prev_idx, int cheb) {
    int r    = blockIdx.x * 8 + (threadIdx.x >> 5);
    int lane = threadIdx.x & 31;
    const uint4* xin  = (const uint4*)&g_feat[in_idx][0];
    uint4*       xout = (uint4*)&g_feat[out_idx][0];

    int e  = g_rowptr[r];
    int e1 = g_rowptr[r + 1];

    float acc[8];
    #pragma unroll
    for (int j = 0; j < 8; ++j) acc[j] = 0.f;

    while (e + 4 <= e1) {
        int   c0 = __ldg(cols + e),     c1 = __ldg(cols + e + 1);
        int   c2 = __ldg(cols + e + 2), c3 = __ldg(cols + e + 3);
        float w0 = __ldg(vals + e),     w1 = __ldg(vals + e + 1);
        float w2 = __ldg(vals + e + 2), w3 = __ldg(vals + e + 3);
        uint4 t0 = xin[(size_t)c0 * 32 + lane];
        uint4 t1 = xin[(size_t)c1 * 32 + lane];
        uint4 t2 = xin[(size_t)c2 * 32 + lane];
        uint4 t3 = xin[(size_t)c3 * 32 + lane];
        acc_edge(acc, t0, w0);
        acc_edge(acc, t1, w1);
        acc_edge(acc, t2, w2);
        acc_edge(acc, t3, w3);
        e += 4;
    }
    while (e < e1) {
        int   c = __ldg(cols + e);
        float w = __ldg(vals + e);
        uint4 t = xin[(size_t)c * 32 + lane];
        acc_edge(acc, t, w);
        ++e;
    }

    size_t o = (size_t)r * 32 + lane;
    if (cheb) {
        uint4 pv = ((const uint4*)&g_feat[prev_idx][0])[o];
        const half2* h = (const half2*)&pv;
        #pragma unroll
        for (int j = 0; j < 4; ++j) {
            float2 f = __half22float2(h[j]);
            acc[2*j]   = 2.f * acc[2*j]   - f.x;
            acc[2*j+1] = 2.f * acc[2*j+1] - f.y;
        }
    }
    uint4 res;
    half2* rh = (half2*)&res;
    #pragma unroll
    for (int j = 0; j < 4; ++j)
        rh[j] = __floats2half2_rn(acc[2*j], acc[2*j+1]);
    xout[o] = res;
}

// ---------------------------------------------------------------------------
// 4) fp16 tensor-core GEMM, 128x128 block tile, ldmatrix + cp.async pipeline.
//    256 threads = 8 warps (4 m-warps x 2 n-warps); warp tile 32x64.
//    1 CTA/SM, uncapped registers (avoid spill from the 128-reg cap).
// ---------------------------------------------------------------------------
#define ASH 72                              // halfs per A smem row (64 + 8 pad)
#define WSH 72                              // halfs per W smem row
#define CSF 132                             // floats per C staging row (EVEN)
#define ABUF_BYTES (128 * ASH * 2)          // 18432
#define WBUF_BYTES (128 * WSH * 2)          // 18432
#define GEMM_SMEM  (2 * ABUF_BYTES + 2 * WBUF_BYTES)   // 73728
// C staging (64 rows x CSF floats = 33792 B) aliases the A/W buffers.

__device__ __forceinline__ void mma_f16(float c[4],
                                        uint32_t a0, uint32_t a1, uint32_t a2, uint32_t a3,
                                        uint32_t b0, uint32_t b1) {
    asm volatile(
        "mma.sync.aligned.m16n8k16.row.col.f32.f16.f16.f32 "
        "{%0,%1,%2,%3}, {%4,%5,%6,%7}, {%8,%9}, {%0,%1,%2,%3};"
        : "+f"(c[0]), "+f"(c[1]), "+f"(c[2]), "+f"(c[3])
        : "r"(a0), "r"(a1), "r"(a2), "r"(a3), "r"(b0), "r"(b1));
}

__device__ __forceinline__ void ldsm4(uint32_t f[4], uint32_t addr) {
    asm volatile("ldmatrix.sync.aligned.m8n8.x4.shared.b16 {%0,%1,%2,%3}, [%4];"
                 : "=r"(f[0]), "=r"(f[1]), "=r"(f[2]), "=r"(f[3]) : "r"(addr));
}

__device__ __forceinline__ void cp_async16(uint32_t dst, const void* src) {
    asm volatile("cp.async.cg.shared.global [%0], [%1], 16;" :: "r"(dst), "l"(src));
}
__device__ __forceinline__ void cp_commit() {
    asm volatile("cp.async.commit_group;");
}
template <int N>
__device__ __forceinline__ void cp_wait() {
    asm volatile("cp.async.wait_group %0;" :: "n"(N));
}

__global__ __launch_bounds__(256, 1)
void gemm_kernel(const float* __restrict__ bias, float* __restrict__ out) {
    extern __shared__ char smem_raw[];
    uint32_t smem_u32 = (uint32_t)__cvta_generic_to_shared(smem_raw);
    float* Cs = (float*)smem_raw;   // aliased staging, [64][CSF]

    int tid  = threadIdx.x;
    int wid  = tid >> 5, lane = tid & 31;
    int wm   = wid & 3;        // m-warp: rows wm*32 .. wm*32+31
    int wn   = wid >> 2;       // n-warp: cols wn*64 .. wn*64+63
    int m0   = blockIdx.x * 128;
    int g    = lane >> 2;      // 0..7
    int tg   = lane & 3;       // 0..3
    int lq   = lane & 15;      // ldmatrix row-select
    int lh   = (lane >> 4) << 3;

    uint32_t aoff[2] = { smem_u32,                smem_u32 + ABUF_BYTES };
    uint32_t woff[2] = { smem_u32 + 2*ABUF_BYTES, smem_u32 + 2*ABUF_BYTES + WBUF_BYTES };

    float acc[2][8][4];
    #pragma unroll
    for (int mt = 0; mt < 2; ++mt)
        #pragma unroll
        for (int nt = 0; nt < 8; ++nt)
            #pragma unroll
            for (int j = 0; j < 4; ++j) acc[mt][nt][j] = 0.f;

    // prefetch helper: panel p into buffer buf
    auto prefetch = [&](int p, int buf) {
        const __half* Ap = &g_feat[p][0];
        #pragma unroll
        for (int i = 0; i < 4; ++i) {
            int idx  = i * 256 + tid;          // 0..1023
            int row  = idx >> 3;               // 0..127
            int col8 = (idx & 7) << 3;
            int rg   = m0 + row; if (rg > M_TOT - 1) rg = M_TOT - 1;
            cp_async16(aoff[buf] + (uint32_t)(row * ASH + col8) * 2,
                       Ap + (size_t)rg * 64 + col8);
        }
        const __half* wp = g_wT + p * (COUT * CIN);
        #pragma unroll
        for (int i = 0; i < 4; ++i) {
            int idx  = i * 256 + tid;
            int o    = idx >> 3;
            int col8 = (idx & 7) << 3;
            cp_async16(woff[buf] + (uint32_t)(o * WSH + col8) * 2,
                       wp + o * 64 + col8);
        }
        cp_commit();
    };

    prefetch(0, 0);

    for (int p = 0; p < KORD; ++p) {
        int cur = p & 1;
        if (p < KORD - 1) prefetch(p + 1, cur ^ 1);
        if (p < KORD - 1) cp_wait<1>(); else cp_wait<0>();
        __syncthreads();

        uint32_t abase = aoff[cur];
        uint32_t wbase = woff[cur];
        #pragma unroll
        for (int ks = 0; ks < 4; ++ks) {
            int kb = ks * 16;
            uint32_t afr[2][4];
            #pragma unroll
            for (int mt = 0; mt < 2; ++mt)
                ldsm4(afr[mt], abase + (uint32_t)((wm*32 + mt*16 + lq) * ASH + kb + lh) * 2);
            uint32_t bfr[4][4];
            #pragma unroll
            for (int bp = 0; bp < 4; ++bp)
                ldsm4(bfr[bp], wbase + (uint32_t)((wn*64 + bp*16 + lq) * WSH + kb + lh) * 2);
            #pragma unroll
            for (int mt = 0; mt < 2; ++mt)
                #pragma unroll
                for (int bp = 0; bp < 4; ++bp) {
                    mma_f16(acc[mt][2*bp],   afr[mt][0], afr[mt][1], afr[mt][2], afr[mt][3],
                            bfr[bp][0], bfr[bp][2]);
                    mma_f16(acc[mt][2*bp+1], afr[mt][0], afr[mt][1], afr[mt][2], afr[mt][3],
                            bfr[bp][1], bfr[bp][3]);
                }
        }
        __syncthreads();
    }

    // Epilogue: two 64-row chunks, staged via smem (aliases A/W buffers).
    #pragma unroll
    for (int ch = 0; ch < 2; ++ch) {
        __syncthreads();
        if ((wm >> 1) == ch) {
            int rbase = (wm & 1) * 32;
            #pragma unroll
            for (int mt = 0; mt < 2; ++mt) {
                int rl = rbase + mt * 16 + g;
                #pragma unroll
                for (int nt = 0; nt < 8; ++nt) {
                    int c0 = wn * 64 + nt * 8 + 2 * tg;
                    *(float2*)(Cs + rl * CSF + c0)       = make_float2(acc[mt][nt][0], acc[mt][nt][1]);
                    *(float2*)(Cs + (rl + 8) * CSF + c0) = make_float2(acc[mt][nt][2], acc[mt][nt][3]);
                }
            }
        }
        __syncthreads();

        int vbase = blockIdx.x * 32 + ch * 16;
        #pragma unroll
        for (int i = 0; i < 8; ++i) {
            int idx = i * 256 + tid;       // 0..2047
            int pr  = idx >> 2;            // (b,o) pair
            int q   = idx & 3;             // v quad
            int b   = pr & 3;
            int o   = pr >> 2;
            int v   = vbase + 4 * q;
            if (v < V) {
                float bv = __ldg(bias + o);
                float4 t;
                t.x = Cs[(16 * q + 0 * 4 + b) * CSF + o] + bv;
                t.y = Cs[(16 * q + 1 * 4 + b) * CSF + o] + bv;
                t.z = Cs[(16 * q + 2 * 4 + b) * CSF + o] + bv;
                t.w = Cs[(16 * q + 3 * 4 + b) * CSF + o] + bv;
                *(float4*)(out + ((size_t)b * COUT + o) * V + v) = t;
            }
        }
    }
}

// ---------------------------------------------------------------------------
// Single stream. Launch order puts gemm_kernel at launch #6 so the ncu
// capture (-s 5 -c 1) profiles the GEMM instead of an SpMM.
// ---------------------------------------------------------------------------
extern "C" void kernel_launch(void* const* d_in, const int* in_sizes, int n_in,
                              void* d_out, int out_size) {
    const float* x    = (const float*)d_in[0];
    const int*   rows = (const int*)  d_in[1];
    const int*   cols = (const int*)  d_in[2];
    const float* vals = (const float*)d_in[3];
    const float* w    = (const float*)d_in[4];
    const float* bias = (const float*)d_in[5];
    float*       out  = (float*)d_out;

    (void)in_sizes; (void)n_in; (void)out_size;

    cudaFuncSetAttribute(gemm_kernel,
                         cudaFuncAttributeMaxDynamicSharedMemorySize, GEMM_SMEM);

    transpose_kernel<<<dim3((V + 31) / 32, 256 / 32), dim3(32, 32)>>>(x);   // 1
    prep_kernel<<<RP_BLOCKS + WC_BLOCKS, 256>>>(rows, w);                   // 2

    spmm_kernel<<<V / 8, 256>>>(cols, vals, 0, 1, 0, 0);  // 3: x1 = L x0
    spmm_kernel<<<V / 8, 256>>>(cols, vals, 1, 2, 0, 1);  // 4: x2 = 2 L x1 - x0
    spmm_kernel<<<V / 8, 256>>>(cols, vals, 2, 3, 1, 1);  // 5: x3 = 2 L x2 - x1

    gemm_kernel<<<(M_TOT + 127) / 128, 256, GEMM_SMEM>>>(bias, out);        // 6
}